// round 3
// baseline (speedup 1.0000x reference)
#include <cuda_runtime.h>
#include <math.h>

#define NN 4096
#define HH 64
#define G4 256
#define TT 48
#define INP 2
#define PP 12
#define RPB 16          // output rows per block in cell kernels
#define ZST 20          // shared z stride (pad 16 -> 20, keeps float4 alignment)
#define MAXNNZ (1 << 21)

// ---------------- static device scratch (no cudaMalloc allowed) ----------------
__device__ float d_h0[2][NN * HH];
__device__ float d_h1[2][NN * HH];
__device__ float d_c0[NN * HH];
__device__ float d_c1[NN * HH];
__device__ float d_Xall[NN * (TT * INP)];   // [n][t*2+k]
__device__ float d_AX[NN * (TT * INP)];     // A @ Xall
__device__ float d_W0[132 * G4];            // rows: liWh0(64) gcWh0(64) liWi0(2) gcWi0(2)
__device__ float d_W1[256 * G4];            // rows: liWi1(64) gcWi1(64) liWh1(64) gcWh1(64)
__device__ float d_b0[G4];
__device__ float d_b1[G4];
__device__ int   d_rowcnt[NN];
__device__ int   d_rowptr[NN + 1];
__device__ float d_dinv[NN];
__device__ int   d_col[MAXNNZ];
__device__ float d_val[MAXNNZ];

// ---------------- adjacency: degree + nnz count ----------------
__global__ void k_degcount(const float* __restrict__ adj) {
    int i = blockIdx.x;
    const float* row = adj + (size_t)i * NN;
    int cnt = 0; float deg = 0.f;
    for (int j = threadIdx.x; j < NN; j += 256) {
        float a = row[j];
        if (j == i) a += 1.f;
        if (a != 0.f) { cnt++; deg += a; }
    }
    __shared__ int   scnt[256];
    __shared__ float sdeg[256];
    scnt[threadIdx.x] = cnt; sdeg[threadIdx.x] = deg;
    __syncthreads();
    for (int s = 128; s > 0; s >>= 1) {
        if (threadIdx.x < s) { scnt[threadIdx.x] += scnt[threadIdx.x + s];
                               sdeg[threadIdx.x] += sdeg[threadIdx.x + s]; }
        __syncthreads();
    }
    if (threadIdx.x == 0) {
        d_rowcnt[i] = scnt[0];
        d_dinv[i] = rsqrtf(sdeg[0]);   // deg >= 1 always (diag +1)
    }
}

// ---------------- exclusive scan of row counts (4096 -> rowptr) ----------------
__global__ void k_scan() {
    __shared__ int ssum[1024];
    int t = threadIdx.x;
    int c0 = d_rowcnt[4 * t], c1 = d_rowcnt[4 * t + 1],
        c2 = d_rowcnt[4 * t + 2], c3 = d_rowcnt[4 * t + 3];
    int s = c0 + c1 + c2 + c3;
    ssum[t] = s;
    __syncthreads();
    for (int off = 1; off < 1024; off <<= 1) {
        int v = (t >= off) ? ssum[t - off] : 0;
        __syncthreads();
        ssum[t] += v;
        __syncthreads();
    }
    int excl = ssum[t] - s;
    d_rowptr[4 * t]     = excl;
    d_rowptr[4 * t + 1] = excl + c0;
    d_rowptr[4 * t + 2] = excl + c0 + c1;
    d_rowptr[4 * t + 3] = excl + c0 + c1 + c2;
    if (t == 1023) d_rowptr[NN] = ssum[1023];
}

// ---------------- deterministic CSR fill (column-sorted) ----------------
__global__ void k_fill(const float* __restrict__ adj) {
    int i = blockIdx.x;
    int tid = threadIdx.x;
    const float* row = adj + (size_t)i * NN;
    float di = d_dinv[i];
    // each thread owns a contiguous 16-column chunk -> deterministic ordering
    int cnt = 0;
    for (int j = tid * 16; j < tid * 16 + 16; j++) {
        float a = row[j] + ((j == i) ? 1.f : 0.f);
        if (a != 0.f) cnt++;
    }
    __shared__ int soff[256];
    soff[tid] = cnt;
    __syncthreads();
    // exclusive scan over 256 thread counts
    for (int off = 1; off < 256; off <<= 1) {
        int v = (tid >= off) ? soff[tid - off] : 0;
        __syncthreads();
        soff[tid] += v;
        __syncthreads();
    }
    int pos = d_rowptr[i] + soff[tid] - cnt;
    for (int j = tid * 16; j < tid * 16 + 16; j++) {
        float a = row[j] + ((j == i) ? 1.f : 0.f);
        if (a != 0.f) {
            d_col[pos] = j;
            d_val[pos] = di * a * d_dinv[j];
            pos++;
        }
    }
}

// ---------------- prep: Xall transpose, zero states, build Wcat/biases ----------------
__global__ void k_prep(const float* __restrict__ x,
                       const float* __restrict__ gcWi0, const float* __restrict__ gcbi0,
                       const float* __restrict__ gcWh0, const float* __restrict__ gcbh0,
                       const float* __restrict__ liWi0, const float* __restrict__ libi0,
                       const float* __restrict__ liWh0, const float* __restrict__ libh0,
                       const float* __restrict__ gcWi1, const float* __restrict__ gcbi1,
                       const float* __restrict__ gcWh1, const float* __restrict__ gcbh1,
                       const float* __restrict__ liWi1, const float* __restrict__ libi1,
                       const float* __restrict__ liWh1, const float* __restrict__ libh1) {
    int id = blockIdx.x * blockDim.x + threadIdx.x;   // grid covers 1<<20
    if (id < NN * (TT * INP)) {
        int n = id / (TT * INP), c = id % (TT * INP);
        int t = c >> 1, k = c & 1;
        d_Xall[id] = x[t * (NN * INP) + n * INP + k];
    }
    if (id < NN * HH) {
        d_h0[0][id] = 0.f; d_h1[0][id] = 0.f;
        d_c0[id] = 0.f;    d_c1[id] = 0.f;
    }
    if (id < 256 * G4) {
        int k = id >> 8, c = id & 255;
        float w1;
        if (k < 64)       w1 = liWi1[k * G4 + c];
        else if (k < 128) w1 = gcWi1[(k - 64) * G4 + c];
        else if (k < 192) w1 = liWh1[(k - 128) * G4 + c];
        else              w1 = gcWh1[(k - 192) * G4 + c];
        d_W1[id] = w1;
        if (k < 132) {
            float w0;
            if (k < 64)       w0 = liWh0[k * G4 + c];
            else if (k < 128) w0 = gcWh0[(k - 64) * G4 + c];
            else if (k < 130) w0 = liWi0[(k - 128) * G4 + c];
            else              w0 = gcWi0[(k - 130) * G4 + c];
            d_W0[k * G4 + c] = w0;
        }
        if (id < G4) {
            d_b0[id] = gcbi0[id] + gcbh0[id] + libi0[id] + libh0[id];
            d_b1[id] = gcbi1[id] + gcbh1[id] + libi1[id] + libh1[id];
        }
    }
}

// ---------------- AX = A @ Xall  ([4096 x 96], once) ----------------
__global__ void k_spmmx() {
    int n = blockIdx.x;
    int c = threadIdx.x;   // 96 threads
    int p0 = d_rowptr[n], p1 = d_rowptr[n + 1];
    float acc = 0.f;
    for (int p = p0; p < p1; p++) {
        acc += d_val[p] * d_Xall[d_col[p] * (TT * INP) + c];
    }
    d_AX[n * (TT * INP) + c] = acc;
}

__device__ __forceinline__ float sigf(float v) { return 1.f / (1.f + expf(-v)); }

// ---------------- fused cell: gather(A@h) + GEMM(z@Wcat+b) + LSTM gates ----------------
// NG==1: layer0  z=[h0, A@h0, x_t(2), (A@x)_t(2)]  K=132
// NG==2: layer1  z=[h0c, A@h0c, h1p, A@h1p]        K=256
template <int NG>
__global__ void __launch_bounds__(256) k_cell(int pr, const float* __restrict__ x, int t) {
    constexpr int K = (NG == 1) ? 132 : 256;
    const float* __restrict__ g1 = (NG == 1) ? d_h0[pr]      : d_h0[pr ^ 1];
    const float* __restrict__ g2 = (NG == 1) ? (const float*)0 : d_h1[pr];
    const float* __restrict__ W  = (NG == 1) ? d_W0 : d_W1;
    const float* __restrict__ bb = (NG == 1) ? d_b0 : d_b1;
    float* __restrict__ cstate   = (NG == 1) ? d_c0 : d_c1;
    float* __restrict__ hout     = (NG == 1) ? d_h0[pr ^ 1] : d_h1[pr ^ 1];

    __shared__ float sh[256 * ZST];   // z^T [k][r], later reused as comb [r][c]
    int tid = threadIdx.x;
    int n0 = blockIdx.x * RPB;

    // plain rows of z: g1 -> k in [0,64)
    #pragma unroll
    for (int i = 0; i < 4; i++) {
        int e = i * 256 + tid;
        int r = e >> 6, k = e & 63;
        sh[k * ZST + r] = g1[(n0 + r) * HH + k];
    }
    if (NG == 2) {
        // g2 plain -> k in [128,192)
        #pragma unroll
        for (int i = 0; i < 4; i++) {
            int e = i * 256 + tid;
            int r = e >> 6, k = e & 63;
            sh[(128 + k) * ZST + r] = g2[(n0 + r) * HH + k];
        }
    } else {
        // x part -> k in [128,132)
        if (tid < RPB) {
            int n = n0 + tid;
            sh[128 * ZST + tid] = x[t * (NN * INP) + n * INP];
            sh[129 * ZST + tid] = x[t * (NN * INP) + n * INP + 1];
            sh[130 * ZST + tid] = d_AX[n * (TT * INP) + 2 * t];
            sh[131 * ZST + tid] = d_AX[n * (TT * INP) + 2 * t + 1];
        }
    }

    // gathered rows: A@g1 -> k in [64,128); (NG==2) A@g2 -> k in [192,256)
    {
        int w = tid >> 5, lane = tid & 31;
        for (int rr = w; rr < RPB; rr += 8) {
            int n = n0 + rr;
            int p0 = d_rowptr[n], p1 = d_rowptr[n + 1];
            float a1x = 0.f, a1y = 0.f, a2x = 0.f, a2y = 0.f;
            for (int p = p0; p < p1; p++) {
                int m = d_col[p];
                float v = d_val[p];
                float2 h2 = *(const float2*)(g1 + m * HH + 2 * lane);
                a1x += v * h2.x; a1y += v * h2.y;
                if (NG == 2) {
                    float2 q2 = *(const float2*)(g2 + m * HH + 2 * lane);
                    a2x += v * q2.x; a2y += v * q2.y;
                }
            }
            sh[(64 + 2 * lane) * ZST + rr]     = a1x;
            sh[(64 + 2 * lane + 1) * ZST + rr] = a1y;
            if (NG == 2) {
                sh[(192 + 2 * lane) * ZST + rr]     = a2x;
                sh[(192 + 2 * lane + 1) * ZST + rr] = a2y;
            }
        }
    }
    __syncthreads();

    // GEMM: comb[r][tid] = b[tid] + sum_k z[r][k] * W[k][tid]
    float acc[RPB];
    {
        float bv = bb[tid];
        #pragma unroll
        for (int r = 0; r < RPB; r++) acc[r] = bv;
        const float* Wc = W + tid;
        #pragma unroll 4
        for (int k = 0; k < K; k++) {
            float wv = Wc[k * G4];
            const float4* z4 = (const float4*)(sh + k * ZST);
            float4 A = z4[0], B = z4[1], C = z4[2], D = z4[3];
            acc[0]  += A.x * wv; acc[1]  += A.y * wv; acc[2]  += A.z * wv; acc[3]  += A.w * wv;
            acc[4]  += B.x * wv; acc[5]  += B.y * wv; acc[6]  += B.z * wv; acc[7]  += B.w * wv;
            acc[8]  += C.x * wv; acc[9]  += C.y * wv; acc[10] += C.z * wv; acc[11] += C.w * wv;
            acc[12] += D.x * wv; acc[13] += D.y * wv; acc[14] += D.z * wv; acc[15] += D.w * wv;
        }
    }
    __syncthreads();   // done reading z
    #pragma unroll
    for (int r = 0; r < RPB; r++) sh[r * G4 + tid] = acc[r];
    __syncthreads();

    // LSTM gates: comb -> (i,f,o,g) -> new c,h
    #pragma unroll
    for (int i = 0; i < 4; i++) {
        int e = i * 256 + tid;
        int r = e >> 6, j = e & 63;
        float ig = sh[r * G4 + j];
        float fg = sh[r * G4 + 64 + j];
        float og = sh[r * G4 + 128 + j];
        float gg = sh[r * G4 + 192 + j];
        int idx = (n0 + r) * HH + j;
        float cold = cstate[idx];
        float nc = sigf(fg) * cold + sigf(ig) * tanhf(gg);
        float nh = sigf(og) * tanhf(nc);
        cstate[idx] = nc;
        hout[idx] = nh;
    }
}

// ---------------- output projection: out = h1 @ outW + outb ----------------
__global__ void k_out(const float* __restrict__ outW, const float* __restrict__ outb,
                      float* __restrict__ out) {
    int g = blockIdx.x * blockDim.x + threadIdx.x;
    if (g >= NN * PP) return;
    int n = g / PP, p = g % PP;
    const float* h = d_h1[0] + n * HH;
    float acc = outb[p];
    #pragma unroll
    for (int k = 0; k < HH; k++) acc += h[k] * outW[k * PP + p];
    out[g] = acc;
}

extern "C" void kernel_launch(void* const* d_in, const int* in_sizes, int n_in,
                              void* d_out, int out_size) {
    const float* x     = (const float*)d_in[0];
    const float* adj   = (const float*)d_in[1];
    const float* gcWi0 = (const float*)d_in[2];
    const float* gcbi0 = (const float*)d_in[3];
    const float* gcWh0 = (const float*)d_in[4];
    const float* gcbh0 = (const float*)d_in[5];
    const float* liWi0 = (const float*)d_in[6];
    const float* libi0 = (const float*)d_in[7];
    const float* liWh0 = (const float*)d_in[8];
    const float* libh0 = (const float*)d_in[9];
    const float* gcWi1 = (const float*)d_in[10];
    const float* gcbi1 = (const float*)d_in[11];
    const float* gcWh1 = (const float*)d_in[12];
    const float* gcbh1 = (const float*)d_in[13];
    const float* liWi1 = (const float*)d_in[14];
    const float* libi1 = (const float*)d_in[15];
    const float* liWh1 = (const float*)d_in[16];
    const float* libh1 = (const float*)d_in[17];
    const float* outW  = (const float*)d_in[18];
    const float* outb  = (const float*)d_in[19];
    float* out = (float*)d_out;

    k_degcount<<<NN, 256>>>(adj);
    k_scan<<<1, 1024>>>();
    k_fill<<<NN, 256>>>(adj);
    k_prep<<<4096, 256>>>(x, gcWi0, gcbi0, gcWh0, gcbh0, liWi0, libi0, liWh0, libh0,
                          gcWi1, gcbi1, gcWh1, gcbh1, liWi1, libi1, liWh1, libh1);
    k_spmmx<<<NN, 96>>>();

    for (int t = 0; t < TT; t++) {
        int pr = t & 1;
        k_cell<1><<<NN / RPB, 256>>>(pr, x, t);
        k_cell<2><<<NN / RPB, 256>>>(pr, x, t);
    }
    k_out<<<(NN * PP + 255) / 256, 256>>>(outW, outb, out);
}

// round 4
// speedup vs baseline: 1.2694x; 1.2694x over previous
#include <cuda_runtime.h>
#include <math.h>

#define NN 4096
#define HH 64
#define G4 256
#define TT 48
#define INP 2
#define PP 12
#define RPB 16          // output rows per block in cell kernels
#define SZD 36          // shared z stride in floats per k (32 duplicated + 4 pad)
#define MAXNNZ (1 << 21)

typedef unsigned long long ull;

// ---------------- static device scratch (no cudaMalloc allowed) ----------------
__device__ float d_h0[2][NN * HH];
__device__ float d_h1[2][NN * HH];
__device__ float d_c0[NN * HH];
__device__ float d_c1[NN * HH];
__device__ float d_Ah0[NN * HH];            // A @ h0_cur, written by layer1, read by layer0 next step
__device__ float d_Xall[NN * (TT * INP)];   // [n][t*2+k]
__device__ float d_AX[NN * (TT * INP)];     // A @ Xall
__device__ float d_W0[132 * G4];            // rows: liWh0(64) gcWh0(64) liWi0(2) gcWi0(2)
__device__ float d_W1[256 * G4];            // rows: liWi1(64) gcWi1(64) liWh1(64) gcWh1(64)
__device__ float d_b0[G4];
__device__ float d_b1[G4];
__device__ int   d_rowcnt[NN];
__device__ int   d_rowptr[NN + 1];
__device__ float d_dinv[NN];
__device__ int   d_col[MAXNNZ];
__device__ float d_val[MAXNNZ];

// ---------------- f32x2 helpers ----------------
__device__ __forceinline__ ull fma2(ull a, ull b, ull c) {
    ull d;
    asm("fma.rn.f32x2 %0, %1, %2, %3;" : "=l"(d) : "l"(a), "l"(b), "l"(c));
    return d;
}

__device__ __forceinline__ float sigf(float v) {
    return __fdividef(1.f, 1.f + __expf(-v));
}
__device__ __forceinline__ float tanhfast(float v) {
    // tanh(x) = 2*sigmoid(2x) - 1
    return __fmaf_rn(2.f, __fdividef(1.f, 1.f + __expf(-2.f * v)), -1.f);
}

// ---------------- adjacency: degree + nnz count ----------------
__global__ void k_degcount(const float* __restrict__ adj) {
    int i = blockIdx.x;
    const float* row = adj + (size_t)i * NN;
    int cnt = 0; float deg = 0.f;
    for (int j = threadIdx.x; j < NN; j += 256) {
        float a = row[j];
        if (j == i) a += 1.f;
        if (a != 0.f) { cnt++; deg += a; }
    }
    __shared__ int   scnt[256];
    __shared__ float sdeg[256];
    scnt[threadIdx.x] = cnt; sdeg[threadIdx.x] = deg;
    __syncthreads();
    for (int s = 128; s > 0; s >>= 1) {
        if (threadIdx.x < s) { scnt[threadIdx.x] += scnt[threadIdx.x + s];
                               sdeg[threadIdx.x] += sdeg[threadIdx.x + s]; }
        __syncthreads();
    }
    if (threadIdx.x == 0) {
        d_rowcnt[i] = scnt[0];
        d_dinv[i] = rsqrtf(sdeg[0]);   // deg >= 1 always (diag +1)
    }
}

// ---------------- exclusive scan of row counts (4096 -> rowptr) ----------------
__global__ void k_scan() {
    __shared__ int ssum[1024];
    int t = threadIdx.x;
    int c0 = d_rowcnt[4 * t], c1 = d_rowcnt[4 * t + 1],
        c2 = d_rowcnt[4 * t + 2], c3 = d_rowcnt[4 * t + 3];
    int s = c0 + c1 + c2 + c3;
    ssum[t] = s;
    __syncthreads();
    for (int off = 1; off < 1024; off <<= 1) {
        int v = (t >= off) ? ssum[t - off] : 0;
        __syncthreads();
        ssum[t] += v;
        __syncthreads();
    }
    int excl = ssum[t] - s;
    d_rowptr[4 * t]     = excl;
    d_rowptr[4 * t + 1] = excl + c0;
    d_rowptr[4 * t + 2] = excl + c0 + c1;
    d_rowptr[4 * t + 3] = excl + c0 + c1 + c2;
    if (t == 1023) d_rowptr[NN] = ssum[1023];
}

// ---------------- deterministic CSR fill (column-sorted) ----------------
__global__ void k_fill(const float* __restrict__ adj) {
    int i = blockIdx.x;
    int tid = threadIdx.x;
    const float* row = adj + (size_t)i * NN;
    float di = d_dinv[i];
    int cnt = 0;
    for (int j = tid * 16; j < tid * 16 + 16; j++) {
        float a = row[j] + ((j == i) ? 1.f : 0.f);
        if (a != 0.f) cnt++;
    }
    __shared__ int soff[256];
    soff[tid] = cnt;
    __syncthreads();
    for (int off = 1; off < 256; off <<= 1) {
        int v = (tid >= off) ? soff[tid - off] : 0;
        __syncthreads();
        soff[tid] += v;
        __syncthreads();
    }
    int pos = d_rowptr[i] + soff[tid] - cnt;
    for (int j = tid * 16; j < tid * 16 + 16; j++) {
        float a = row[j] + ((j == i) ? 1.f : 0.f);
        if (a != 0.f) {
            d_col[pos] = j;
            d_val[pos] = di * a * d_dinv[j];
            pos++;
        }
    }
}

// ---------------- prep: Xall transpose, zero states, build Wcat/biases ----------------
__global__ void k_prep(const float* __restrict__ x,
                       const float* __restrict__ gcWi0, const float* __restrict__ gcbi0,
                       const float* __restrict__ gcWh0, const float* __restrict__ gcbh0,
                       const float* __restrict__ liWi0, const float* __restrict__ libi0,
                       const float* __restrict__ liWh0, const float* __restrict__ libh0,
                       const float* __restrict__ gcWi1, const float* __restrict__ gcbi1,
                       const float* __restrict__ gcWh1, const float* __restrict__ gcbh1,
                       const float* __restrict__ liWi1, const float* __restrict__ libi1,
                       const float* __restrict__ liWh1, const float* __restrict__ libh1) {
    int id = blockIdx.x * blockDim.x + threadIdx.x;   // grid covers 1<<20
    if (id < NN * (TT * INP)) {
        int n = id / (TT * INP), c = id % (TT * INP);
        int t = c >> 1, k = c & 1;
        d_Xall[id] = x[t * (NN * INP) + n * INP + k];
    }
    if (id < NN * HH) {
        d_h0[0][id] = 0.f; d_h1[0][id] = 0.f;
        d_c0[id] = 0.f;    d_c1[id] = 0.f;
        d_Ah0[id] = 0.f;
    }
    if (id < 256 * G4) {
        int k = id >> 8, c = id & 255;
        float w1;
        if (k < 64)       w1 = liWi1[k * G4 + c];
        else if (k < 128) w1 = gcWi1[(k - 64) * G4 + c];
        else if (k < 192) w1 = liWh1[(k - 128) * G4 + c];
        else              w1 = gcWh1[(k - 192) * G4 + c];
        d_W1[id] = w1;
        if (k < 132) {
            float w0;
            if (k < 64)       w0 = liWh0[k * G4 + c];
            else if (k < 128) w0 = gcWh0[(k - 64) * G4 + c];
            else if (k < 130) w0 = liWi0[(k - 128) * G4 + c];
            else              w0 = gcWi0[(k - 130) * G4 + c];
            d_W0[k * G4 + c] = w0;
        }
        if (id < G4) {
            d_b0[id] = gcbi0[id] + gcbh0[id] + libi0[id] + libh0[id];
            d_b1[id] = gcbi1[id] + gcbh1[id] + libi1[id] + libh1[id];
        }
    }
}

// ---------------- AX = A @ Xall  ([4096 x 96], once) ----------------
__global__ void k_spmmx() {
    int n = blockIdx.x;
    int c = threadIdx.x;   // 96 threads
    int p0 = d_rowptr[n], p1 = d_rowptr[n + 1];
    float acc = 0.f;
    for (int p = p0; p < p1; p++) {
        acc += d_val[p] * d_Xall[d_col[p] * (TT * INP) + c];
    }
    d_AX[n * (TT * INP) + c] = acc;
}

// ---------------- shared GEMM + gates body ----------------
// sh holds z^T duplicated: sh[k*SZD + 2r] == sh[k*SZD + 2r + 1] == z[r][k]
// After __syncthreads, sh is reused as comb[r][c] (16 x 256).
template <int K>
__device__ __forceinline__ void gemm_gates(float* sh, const float* __restrict__ W,
                                           const float* __restrict__ bb,
                                           float* __restrict__ cstate,
                                           float* __restrict__ hout,
                                           int n0, int tid) {
    int cg = tid >> 2;          // column group: cols cg*4 .. cg*4+3
    int rg = tid & 3;           // row group:    rows rg*4 .. rg*4+3
    const float* Wp = W + (cg << 2);
    const float* zp = sh + (rg << 3);   // 2*(rg*4) duplicated floats

    ulonglong2 b2 = *(const ulonglong2*)(bb + (cg << 2));   // {b0,b1},{b2,b3} packed
    ull a00 = b2.x, a01 = b2.y;   // row rg*4+0
    ull a10 = b2.x, a11 = b2.y;
    ull a20 = b2.x, a21 = b2.y;
    ull a30 = b2.x, a31 = b2.y;

    #pragma unroll 4
    for (int k = 0; k < K; k++) {
        ulonglong2 w2 = *(const ulonglong2*)(Wp + k * G4);          // {w0,w1},{w2,w3}
        ulonglong2 zA = *(const ulonglong2*)(zp + k * SZD);         // {z0,z0},{z1,z1}
        ulonglong2 zB = *(const ulonglong2*)(zp + k * SZD + 4);     // {z2,z2},{z3,z3}
        a00 = fma2(zA.x, w2.x, a00); a01 = fma2(zA.x, w2.y, a01);
        a10 = fma2(zA.y, w2.x, a10); a11 = fma2(zA.y, w2.y, a11);
        a20 = fma2(zB.x, w2.x, a20); a21 = fma2(zB.x, w2.y, a21);
        a30 = fma2(zB.y, w2.x, a30); a31 = fma2(zB.y, w2.y, a31);
    }
    __syncthreads();   // everyone done reading z

    // write comb[r][c] = sh[r*G4 + c]
    {
        float* base = sh + (rg << 2) * G4 + (cg << 2);
        *(ulonglong2*)(base)          = make_ulonglong2(a00, a01);
        *(ulonglong2*)(base + G4)     = make_ulonglong2(a10, a11);
        *(ulonglong2*)(base + 2 * G4) = make_ulonglong2(a20, a21);
        *(ulonglong2*)(base + 3 * G4) = make_ulonglong2(a30, a31);
    }
    __syncthreads();

    // LSTM gates
    #pragma unroll
    for (int i = 0; i < 4; i++) {
        int e = i * 256 + tid;
        int r = e >> 6, j = e & 63;
        float ig = sh[r * G4 + j];
        float fg = sh[r * G4 + 64 + j];
        float og = sh[r * G4 + 128 + j];
        float gg = sh[r * G4 + 192 + j];
        int idx = (n0 + r) * HH + j;
        float cold = cstate[idx];
        float nc = sigf(fg) * cold + sigf(ig) * tanhfast(gg);
        float nh = sigf(og) * tanhfast(nc);
        cstate[idx] = nc;
        hout[idx] = nh;
    }
}

// ---------------- layer 0 cell: all-plain z (no gather!) ----------------
// z = [h0_prev(64), Ah0_saved(64), x_t(2), Ax_t(2)]  K=132
__global__ void __launch_bounds__(256) k_cell0(int pr, const float* __restrict__ x, int t) {
    __shared__ float sh[132 * SZD];   // 4752 floats >= 16*256 comb
    int tid = threadIdx.x;
    int n0 = blockIdx.x * RPB;
    const float* __restrict__ g1 = d_h0[pr];

    #pragma unroll
    for (int i = 0; i < 4; i++) {
        int e = i * 256 + tid;
        int r = e >> 6, k = e & 63;
        float v1 = g1[(n0 + r) * HH + k];
        float v2 = d_Ah0[(n0 + r) * HH + k];
        *(float2*)(sh + k * SZD + 2 * r)        = make_float2(v1, v1);
        *(float2*)(sh + (64 + k) * SZD + 2 * r) = make_float2(v2, v2);
    }
    if (tid < RPB) {
        int n = n0 + tid;
        float x0 = x[t * (NN * INP) + n * INP];
        float x1 = x[t * (NN * INP) + n * INP + 1];
        float ax0 = d_AX[n * (TT * INP) + 2 * t];
        float ax1 = d_AX[n * (TT * INP) + 2 * t + 1];
        *(float2*)(sh + 128 * SZD + 2 * tid) = make_float2(x0, x0);
        *(float2*)(sh + 129 * SZD + 2 * tid) = make_float2(x1, x1);
        *(float2*)(sh + 130 * SZD + 2 * tid) = make_float2(ax0, ax0);
        *(float2*)(sh + 131 * SZD + 2 * tid) = make_float2(ax1, ax1);
    }
    __syncthreads();

    gemm_gates<132>(sh, d_W0, d_b0, d_c0, d_h0[pr ^ 1], n0, tid);
}

// ---------------- layer 1 cell: gather A@h0_cur (saved to d_Ah0) + A@h1_prev ----------------
// z = [h0_cur(64), A@h0_cur(64), h1_prev(64), A@h1_prev(64)]  K=256
__global__ void __launch_bounds__(256) k_cell1(int pr) {
    __shared__ float sh[256 * SZD];   // 9216 floats
    int tid = threadIdx.x;
    int n0 = blockIdx.x * RPB;
    const float* __restrict__ g1 = d_h0[pr ^ 1];   // h0 current
    const float* __restrict__ g2 = d_h1[pr];       // h1 previous

    #pragma unroll
    for (int i = 0; i < 4; i++) {
        int e = i * 256 + tid;
        int r = e >> 6, k = e & 63;
        float v1 = g1[(n0 + r) * HH + k];
        float v2 = g2[(n0 + r) * HH + k];
        *(float2*)(sh + k * SZD + 2 * r)         = make_float2(v1, v1);
        *(float2*)(sh + (128 + k) * SZD + 2 * r) = make_float2(v2, v2);
    }

    // gather phase: 8 warps, 2 rows each
    {
        int w = tid >> 5, lane = tid & 31;
        #pragma unroll
        for (int half = 0; half < 2; half++) {
            int rr = w + half * 8;
            int n = n0 + rr;
            int p0 = d_rowptr[n], p1 = d_rowptr[n + 1];
            float a1x = 0.f, a1y = 0.f, a2x = 0.f, a2y = 0.f;
            float b1x = 0.f, b1y = 0.f, b2x = 0.f, b2y = 0.f;
            int p = p0;
            for (; p + 1 < p1; p += 2) {
                int m0 = d_col[p];       int m1 = d_col[p + 1];
                float v0 = d_val[p];     float v1 = d_val[p + 1];
                float2 h0a = *(const float2*)(g1 + m0 * HH + 2 * lane);
                float2 q0a = *(const float2*)(g2 + m0 * HH + 2 * lane);
                float2 h1a = *(const float2*)(g1 + m1 * HH + 2 * lane);
                float2 q1a = *(const float2*)(g2 + m1 * HH + 2 * lane);
                a1x += v0 * h0a.x; a1y += v0 * h0a.y;
                a2x += v0 * q0a.x; a2y += v0 * q0a.y;
                b1x += v1 * h1a.x; b1y += v1 * h1a.y;
                b2x += v1 * q1a.x; b2y += v1 * q1a.y;
            }
            if (p < p1) {
                int m0 = d_col[p]; float v0 = d_val[p];
                float2 h0a = *(const float2*)(g1 + m0 * HH + 2 * lane);
                float2 q0a = *(const float2*)(g2 + m0 * HH + 2 * lane);
                a1x += v0 * h0a.x; a1y += v0 * h0a.y;
                a2x += v0 * q0a.x; a2y += v0 * q0a.y;
            }
            a1x += b1x; a1y += b1y; a2x += b2x; a2y += b2y;

            *(float2*)(sh + (64 + 2 * lane) * SZD + 2 * rr)      = make_float2(a1x, a1x);
            *(float2*)(sh + (64 + 2 * lane + 1) * SZD + 2 * rr)  = make_float2(a1y, a1y);
            *(float2*)(sh + (192 + 2 * lane) * SZD + 2 * rr)     = make_float2(a2x, a2x);
            *(float2*)(sh + (192 + 2 * lane + 1) * SZD + 2 * rr) = make_float2(a2y, a2y);
            // save A@h0_cur for next step's layer0
            *(float2*)(d_Ah0 + n * HH + 2 * lane) = make_float2(a1x, a1y);
        }
    }
    __syncthreads();

    gemm_gates<256>(sh, d_W1, d_b1, d_c1, d_h1[pr ^ 1], n0, tid);
}

// ---------------- output projection: out = h1 @ outW + outb ----------------
__global__ void k_out(const float* __restrict__ outW, const float* __restrict__ outb,
                      float* __restrict__ out) {
    int g = blockIdx.x * blockDim.x + threadIdx.x;
    if (g >= NN * PP) return;
    int n = g / PP, p = g % PP;
    const float* h = d_h1[0] + n * HH;
    float acc = outb[p];
    #pragma unroll
    for (int k = 0; k < HH; k++) acc += h[k] * outW[k * PP + p];
    out[g] = acc;
}

extern "C" void kernel_launch(void* const* d_in, const int* in_sizes, int n_in,
                              void* d_out, int out_size) {
    const float* x     = (const float*)d_in[0];
    const float* adj   = (const float*)d_in[1];
    const float* gcWi0 = (const float*)d_in[2];
    const float* gcbi0 = (const float*)d_in[3];
    const float* gcWh0 = (const float*)d_in[4];
    const float* gcbh0 = (const float*)d_in[5];
    const float* liWi0 = (const float*)d_in[6];
    const float* libi0 = (const float*)d_in[7];
    const float* liWh0 = (const float*)d_in[8];
    const float* libh0 = (const float*)d_in[9];
    const float* gcWi1 = (const float*)d_in[10];
    const float* gcbi1 = (const float*)d_in[11];
    const float* gcWh1 = (const float*)d_in[12];
    const float* gcbh1 = (const float*)d_in[13];
    const float* liWi1 = (const float*)d_in[14];
    const float* libi1 = (const float*)d_in[15];
    const float* liWh1 = (const float*)d_in[16];
    const float* libh1 = (const float*)d_in[17];
    const float* outW  = (const float*)d_in[18];
    const float* outb  = (const float*)d_in[19];
    float* out = (float*)d_out;

    k_degcount<<<NN, 256>>>(adj);
    k_scan<<<1, 1024>>>();
    k_fill<<<NN, 256>>>(adj);
    k_prep<<<4096, 256>>>(x, gcWi0, gcbi0, gcWh0, gcbh0, liWi0, libi0, liWh0, libh0,
                          gcWi1, gcbi1, gcWh1, gcbh1, liWi1, libi1, liWh1, libh1);
    k_spmmx<<<NN, 96>>>();

    for (int t = 0; t < TT; t++) {
        int pr = t & 1;
        k_cell0<<<NN / RPB, 256>>>(pr, x, t);
        k_cell1<<<NN / RPB, 256>>>(pr);
    }
    k_out<<<(NN * PP + 255) / 256, 256>>>(outW, outb, out);
}